// round 14
// baseline (speedup 1.0000x reference)
#include <cuda_runtime.h>
#include <cuda_bf16.h>

#define DEVFN static __device__ __forceinline__

namespace {
constexpr int L_ = 512, NB = 64, IND = 256, HD = 1024;
constexpr unsigned NH = (unsigned)NB * HD;                        // 65536
constexpr unsigned ALLC_OFF = (unsigned)L_ * NH;                  // 33554432
constexpr unsigned HN_OFF = ALLC_OFF + (unsigned)L_ * 2u * NH;    // 100663296
constexpr unsigned CN_OFF = HN_OFF + 2u * NH;
constexpr unsigned XSZ = (unsigned)L_ * NB * (IND / 2);           // 4194304 u32 per plane
// dynamic smem layout (u32 units): deep A ring, deep B ring, exchange
constexpr int AS_STAGE = 2560;             // 2 planes x 64 rows x 20 (16 data + 4 pad)
constexpr int A_STAGES = 6;
constexpr int AS_TOT   = A_STAGES * AS_STAGE;      // 15360
constexpr int BS_STAGE = 2048;             // 8 KB weights per chunk
constexpr int B_STAGES = 12;
constexpr int BS_OFF   = AS_TOT;                   // 15360
constexpr int EXCH_OFF = BS_OFF + B_STAGES * BS_STAGE;   // 39936
constexpr int SMEM_U32 = EXCH_OFF + 2048;                // 41984 u32 = 164 KB
}

// Persistent scratch (static __device__ allocation — sanctioned pattern).
__device__ __align__(16) unsigned g_Wp0[64 * 80 * 1024];    // layer0 packed bf16-split weights
__device__ __align__(16) unsigned g_Wp1[64 * 128 * 1024];   // layer1
__device__ __align__(16) unsigned g_xs[2 * XSZ];            // x split planes (hi, lo)
__device__ __align__(16) unsigned g_h0s[2][2][64 * 512];    // [parity][plane] h layer0, packed bf16x2
__device__ __align__(16) unsigned g_h1s[2][2][64 * 512];    // h layer1
__device__ unsigned g_bar;                                  // grid barrier (monotonic)

// Split fp32 pair into packed bf16x2 hi and lo planes.
DEVFN void split2(float x0, float x1, unsigned& hi, unsigned& lo) {
    __nv_bfloat16 h0 = __float2bfloat16(x0), h1 = __float2bfloat16(x1);
    float r0 = x0 - __bfloat162float(h0), r1 = x1 - __bfloat162float(h1);
    __nv_bfloat16 l0 = __float2bfloat16(r0), l1 = __float2bfloat16(r1);
    hi = (unsigned)__bfloat16_as_ushort(h0) | ((unsigned)__bfloat16_as_ushort(h1) << 16);
    lo = (unsigned)__bfloat16_as_ushort(l0) | ((unsigned)__bfloat16_as_ushort(l1) << 16);
}

DEVFN void mma16816(float* c, const unsigned* a, unsigned b0, unsigned b1) {
    asm volatile(
        "mma.sync.aligned.m16n8k16.row.col.f32.bf16.bf16.f32 "
        "{%0,%1,%2,%3}, {%4,%5,%6,%7}, {%8,%9}, {%0,%1,%2,%3};\n"
        : "+f"(c[0]), "+f"(c[1]), "+f"(c[2]), "+f"(c[3])
        : "r"(a[0]), "r"(a[1]), "r"(a[2]), "r"(a[3]), "r"(b0), "r"(b1));
}

DEVFN void cp16(void* sdst, const void* gsrc) {
    unsigned s = (unsigned)__cvta_generic_to_shared(sdst);
    asm volatile("cp.async.cg.shared.global [%0], [%1], 16;\n" :: "r"(s), "l"(gsrc));
}
DEVFN void cp_commit() { asm volatile("cp.async.commit_group;\n"); }
template <int N> DEVFN void cp_wait() { asm volatile("cp.async.wait_group %0;\n" :: "n"(N)); }

DEVFN float sigf(float x) { return 1.f / (1.f + __expf(-x)); }
DEVFN float tanhf_(float x) {
    float a = fabsf(x);
    float e = __expf(-2.f * a);
    return copysignf((1.f - e) / (1.f + e), x);
}

// ---------------------------------------------------------------------------
// Reset barrier + split initial h state into the correct parity slots.
// layer0 reads parity 1 at epoch 0; layer1 reads parity 0 at epoch 1.
// ---------------------------------------------------------------------------
__global__ void init_kernel(const float* __restrict__ h0) {
    unsigned i = blockIdx.x * blockDim.x + threadIdx.x;
    if (i == 0) g_bar = 0u;
    const float2* h2 = (const float2*)h0;
    for (; i < 2u * 64u * 512u; i += gridDim.x * blockDim.x) {
        float2 v = h2[i];
        unsigned hi, lo;
        split2(v.x, v.y, hi, lo);
        if (i < 64u * 512u) { g_h0s[1][0][i] = hi; g_h0s[1][1][i] = lo; }
        else { g_h1s[0][0][i - 64u * 512u] = hi; g_h1s[0][1][i - 64u * 512u] = lo; }
    }
}

// Pre-split x into bf16 hi/lo planes (packed pairs), layout (t, n, kpair).
__global__ void xsplit_kernel(const float* __restrict__ x) {
    const float2* x2 = (const float2*)x;
    for (unsigned i = blockIdx.x * blockDim.x + threadIdx.x; i < XSZ;
         i += gridDim.x * blockDim.x) {
        float2 v = x2[i];
        unsigned hi, lo;
        split2(v.x, v.y, hi, lo);
        g_xs[i] = hi;
        g_xs[XSZ + i] = lo;
    }
}

// ---------------------------------------------------------------------------
// Pack weights into mma-B-fragment-exact, gate-interleaved, bf16-split layout.
// u32 at (((c*S16+s)*8+blk)*2+plane)*64 + lane*2 + bsel packs bf16x2 of
// W[row][k0], W[row][k0+1] with k0 = s*16 + (lane&3)*2 + bsel*8,
// col = blk*8 + (lane>>2), gate = col>>4, cell = c*16 + (col&15),
// row = gate*H + cell;  k < Din -> w_ih else w_hh (K = [input ; hidden]).
// ---------------------------------------------------------------------------
__global__ void permute_kernel(
    const float* __restrict__ wih0, const float* __restrict__ whh0,
    const float* __restrict__ wih1, const float* __restrict__ whh1)
{
    const int tot0 = 64 * 80 * 1024;
    const int tot1 = 64 * 128 * 1024;
    for (int idx = blockIdx.x * blockDim.x + threadIdx.x; idx < tot0 + tot1;
         idx += gridDim.x * blockDim.x) {
        const int layer = idx >= tot0 ? 1 : 0;
        const int li = layer ? idx - tot0 : idx;
        const int S16 = layer ? 128 : 80;
        const int Din = layer ? HD : IND;
        const float* wih = layer ? wih1 : wih0;
        const float* whh = layer ? whh1 : whh0;
        const int per_c = S16 * 1024;
        const int c = li / per_c;
        const int rem = li - c * per_c;
        const int s = rem >> 10;
        const int r2 = rem & 1023;
        const int blk = r2 >> 7;
        const int r3 = r2 & 127;
        const int plane = r3 >> 6;
        const int r4 = r3 & 63;
        const int lane = r4 >> 1, bsel = r4 & 1;
        const int k0 = s * 16 + (lane & 3) * 2 + bsel * 8;
        const int col = blk * 8 + (lane >> 2);
        const int row = (col >> 4) * HD + c * 16 + (col & 15);
        float v0, v1;
        if (k0 < Din) { v0 = wih[row * Din + k0]; v1 = wih[row * Din + k0 + 1]; }
        else          { v0 = whh[row * HD + k0 - Din]; v1 = whh[row * HD + k0 + 1 - Din]; }
        unsigned hi, lo;
        split2(v0, v1, hi, lo);
        const unsigned val = plane ? lo : hi;
        if (layer) g_Wp1[li] = val;
        else       g_Wp0[li] = val;
    }
}

// ---------------------------------------------------------------------------
// Persistent LSTM. 128 CTAs x 256 threads. CTA = (layer = bid>>6, cblk = bid&63).
// Deep split prefetch rings: A (activations) 6 stages, B (weights) 12 stages.
// Group stream per epoch: prologue g0..g10 = {A(p)|p<5, B(p)|p<11}; loop iter
// ch issues g(11+ch) = {A(ch+5), B(ch+11)} then computes chunk ch after
// wait_group<4> (A(ch) lands in g(ch+6) = done-through boundary) + sync.
// Warps split gate blocks: wq=0 -> i,f; wq=1 -> g,o (exchange via smem).
// ---------------------------------------------------------------------------
__global__ void __launch_bounds__(256, 1) lstm_kernel(
    const float* __restrict__ c0,
    const float* __restrict__ bih0, const float* __restrict__ bhh0,
    const float* __restrict__ bih1, const float* __restrict__ bhh1,
    float* __restrict__ out)
{
    extern __shared__ unsigned smem[];

    const int layer = blockIdx.x >> 6;
    const int cblk = blockIdx.x & 63;
    const int tid = threadIdx.x;
    const int wq = tid >> 7;            // 0: i,f blocks   1: g,o blocks
    const int w4 = (tid >> 5) & 3;      // row-warp (16 batch rows each)
    const int lane = tid & 31;
    const int g = lane >> 2, t = lane & 3;
    const int S16 = layer ? 128 : 80;
    const int nch = layer ? 64 : 40;    // 32-wide K chunks
    const unsigned* __restrict__ Wp = layer ? g_Wp1 : g_Wp0;
    const float* bih = layer ? bih1 : bih0;
    const float* bhh = layer ? bhh1 : bhh0;

    float2 bias[4];
#pragma unroll
    for (int b = 0; b < 4; b++) {
        const int blk = wq * 4 + b;
        const int r = (blk >> 1) * HD + cblk * 16 + (blk & 1) * 8 + t * 2;
        bias[b].x = bih[r] + bhh[r];
        bias[b].y = bih[r + 1] + bhh[r + 1];
    }
    float cst[8];
#pragma unroll
    for (int rho = 0; rho < 2; rho++)
#pragma unroll
        for (int p = 0; p < 2; p++)
#pragma unroll
            for (int q = 0; q < 2; q++) {
                const int n = 16 * w4 + g + 8 * rho;
                const int cell = cblk * 16 + p * 8 + t * 2 + q;
                cst[rho * 4 + p * 2 + q] = c0[(unsigned)layer * NH + (unsigned)n * HD + cell];
            }

    float* exch = (float*)(smem + EXCH_OFF);

    for (int e = 0; e <= 512; e++) {
        const int tstep = layer ? e - 1 : e;
        const bool active = layer ? (e >= 1) : (e < 512);
        const int rs = 1 - (e & 1), ws = e & 1;
        if (active) {
            float acc[4][4];
#pragma unroll
            for (int b = 0; b < 4; b++) {
                acc[b][0] = acc[b][2] = bias[b].x;
                acc[b][1] = acc[b][3] = bias[b].y;
            }

            // A-tile load: chunk ch -> stage ch % A_STAGES (2 cp16/thread).
            auto load_A = [&](int ch) {
                const int kp0 = ch * 16;
                unsigned* sb = smem + (ch % A_STAGES) * AS_STAGE;
#pragma unroll
                for (int i = 0; i < 2; i++) {
                    const int id = tid + i * 256;   // 0..511
                    const int plane = id >> 8;
                    const int r2 = id & 255;
                    const int row = r2 >> 2, seg = r2 & 3;
                    const unsigned* asrc;
                    if (layer == 0) {
                        if (kp0 < 128)
                            asrc = g_xs + (unsigned)plane * XSZ +
                                   ((unsigned)tstep * 64 + row) * 128 + kp0;
                        else
                            asrc = g_h0s[rs][plane] + row * 512 + (kp0 - 128);
                    } else {
                        if (kp0 < 512)
                            asrc = g_h0s[rs][plane] + row * 512 + kp0;
                        else
                            asrc = g_h1s[rs][plane] + row * 512 + (kp0 - 512);
                    }
                    cp16(sb + plane * 1280 + row * 20 + seg * 4, asrc + seg * 4);
                }
            };
            // Weight-tile load: chunk ch -> stage ch % B_STAGES (2 cp16/thread).
            auto load_B = [&](int ch) {
                unsigned* bb = smem + BS_OFF + (ch % B_STAGES) * BS_STAGE;
                const unsigned* bsrc = Wp + ((unsigned)cblk * S16 + ch * 2) * 1024u;
#pragma unroll
                for (int i = 0; i < 2; i++) {
                    const int id = tid + i * 256;
                    cp16(bb + id * 4, bsrc + id * 4);
                }
            };

            cp_wait<0>();   // drain stragglers from previous epoch (instant)
            // prologue: 11 groups priming A depth 5, B depth 11
            for (int p = 0; p < 11; p++) {
                if (p < 5) load_A(p);
                load_B(p);          // p < 11 <= nch always
                cp_commit();
            }

            for (int ch = 0; ch < nch; ch++) {
                cp_wait<4>();       // data for chunk ch complete (this thread)
                __syncthreads();    // visible to all; stages (ch-1)%6/(ch-1)%12 free
                {
                    const int a = ch + 5;
                    if (a < nch) load_A(a);
                    const int b = ch + 11;
                    if (b < nch) load_B(b);
                    cp_commit();    // always commit: constant group numbering
                }
                const unsigned* as_ = smem + (ch % A_STAGES) * AS_STAGE;
                const unsigned* bs_ = smem + BS_OFF + (ch % B_STAGES) * BS_STAGE;
                const int arow = (16 * w4 + g) * 20;
#pragma unroll
                for (int sl = 0; sl < 2; sl++) {
                    const int ab = arow + sl * 8 + t;
                    unsigned ahi[4], alo[4];
                    ahi[0] = as_[ab];            ahi[1] = as_[ab + 160];
                    ahi[2] = as_[ab + 4];        ahi[3] = as_[ab + 164];
                    alo[0] = as_[ab + 1280];     alo[1] = as_[ab + 1440];
                    alo[2] = as_[ab + 1284];     alo[3] = as_[ab + 1444];
#pragma unroll
                    for (int b = 0; b < 4; b++) {
                        const unsigned* bb2 = bs_ + (sl * 8 + wq * 4 + b) * 128 + lane * 2;
                        const uint2 bh = *(const uint2*)bb2;
                        const uint2 bl = *(const uint2*)(bb2 + 64);
                        mma16816(acc[b], ahi, bh.x, bh.y);   // hi*hi
                        mma16816(acc[b], ahi, bl.x, bl.y);   // hi*lo
                        mma16816(acc[b], alo, bh.x, bh.y);   // lo*hi
                    }
                }
            }
            __syncthreads();   // all compute done

            // ---- gate exchange: wq==1 ships raw g,o pre-activations ----
            if (wq == 1) {
                const int col = w4 * 32 + lane;
#pragma unroll
                for (int b = 0; b < 4; b++)
#pragma unroll
                    for (int idx = 0; idx < 4; idx++)
                        exch[(b * 4 + idx) * 128 + col] = acc[b][idx];
            }
            __syncthreads();

            // ---- fused LSTM pointwise (wq==0 threads) ----
            if (wq == 0) {
                const int col = w4 * 32 + lane;
                unsigned (*hs)[64 * 512] = layer ? g_h1s[ws] : g_h0s[ws];
#pragma unroll
                for (int rho = 0; rho < 2; rho++) {
                    const int n = 16 * w4 + g + 8 * rho;
#pragma unroll
                    for (int p = 0; p < 2; p++) {
                        const int cell = cblk * 16 + p * 8 + t * 2;
                        float2 h2, c2;
#pragma unroll
                        for (int q = 0; q < 2; q++) {
                            const int idx = rho * 2 + q;
                            const float ii = sigf(acc[0 + p][idx]);
                            const float ff = sigf(acc[2 + p][idx]);
                            const float gg = tanhf_(exch[((0 + p) * 4 + idx) * 128 + col]);
                            const float oo = sigf(exch[((2 + p) * 4 + idx) * 128 + col]);
                            const int cs = rho * 4 + p * 2 + q;
                            const float cc = ff * cst[cs] + ii * gg;
                            cst[cs] = cc;
                            const float hh = oo * tanhf_(cc);
                            if (q) { h2.y = hh; c2.y = cc; } else { h2.x = hh; c2.x = cc; }
                        }
                        unsigned hhi, hlo;
                        split2(h2.x, h2.y, hhi, hlo);
                        const unsigned kp = (unsigned)n * 512 + (cell >> 1);
                        hs[0][kp] = hhi;
                        hs[1][kp] = hlo;
                        *(float2*)&out[ALLC_OFF + ((unsigned)(tstep * 2 + layer) * NB + n) * HD + cell] = c2;
                        if (layer)
                            *(float2*)&out[((unsigned)tstep * NB + n) * HD + cell] = h2;
                        if (tstep == 511) {
                            *(float2*)&out[HN_OFF + ((unsigned)layer * NB + n) * HD + cell] = h2;
                            *(float2*)&out[CN_OFF + ((unsigned)layer * NB + n) * HD + cell] = c2;
                        }
                    }
                }
            }
        }
        if (e < 512) {   // grid barrier (monotonic; init resets g_bar)
            __threadfence();
            __syncthreads();
            if (tid == 0) {
                atomicAdd(&g_bar, 1u);
                const unsigned target = (unsigned)(e + 1) * 128u;
                unsigned v;
                do {
                    asm volatile("ld.acquire.gpu.u32 %0, [%1];" : "=r"(v) : "l"(&g_bar));
                    if (v >= target) break;
                    __nanosleep(32);
                } while (true);
            }
            __syncthreads();
        }
    }
}

extern "C" void kernel_launch(void* const* d_in, const int* in_sizes, int n_in,
                              void* d_out, int out_size) {
    (void)in_sizes; (void)n_in; (void)out_size;
    const float* x    = (const float*)d_in[0];
    const float* h0   = (const float*)d_in[1];
    const float* c0   = (const float*)d_in[2];
    const float* wih0 = (const float*)d_in[3];
    const float* whh0 = (const float*)d_in[4];
    const float* bih0 = (const float*)d_in[5];
    const float* bhh0 = (const float*)d_in[6];
    const float* wih1 = (const float*)d_in[7];
    const float* whh1 = (const float*)d_in[8];
    const float* bih1 = (const float*)d_in[9];
    const float* bhh1 = (const float*)d_in[10];
    float* out = (float*)d_out;

    static bool attr_set = false;
    if (!attr_set) {
        cudaFuncSetAttribute(lstm_kernel, cudaFuncAttributeMaxDynamicSharedMemorySize,
                             SMEM_U32 * 4);
        attr_set = true;
    }

    init_kernel<<<64, 256>>>(h0);
    xsplit_kernel<<<2048, 256>>>(x);
    permute_kernel<<<4096, 256>>>(wih0, whh0, wih1, whh1);
    lstm_kernel<<<128, 256, SMEM_U32 * 4>>>(c0, bih0, bhh0, bih1, bhh1, out);
}

// round 16
// speedup vs baseline: 1.7863x; 1.7863x over previous
#include <cuda_runtime.h>
#include <cuda_fp16.h>

#define DEVFN static __device__ __forceinline__

namespace {
constexpr int L_ = 512, NB = 64, IND = 256, HD = 1024;
constexpr unsigned NH = (unsigned)NB * HD;                        // 65536
constexpr unsigned ALLC_OFF = (unsigned)L_ * NH;                  // 33554432
constexpr unsigned HN_OFF = ALLC_OFF + (unsigned)L_ * 2u * NH;    // 100663296
constexpr unsigned CN_OFF = HN_OFF + 2u * NH;
constexpr unsigned XSZ = (unsigned)L_ * NB * (IND / 2);           // 4194304 u32 (fp16 pairs)
// dynamic smem layout (u32 units)
constexpr int AS_STAGE = 64 * 20;          // 64 rows x (16 data pairs + 4 pad)
constexpr int AS_TOT   = 4 * AS_STAGE;     // 5120
constexpr int BS_STAGE = 1024;             // 2 k16-steps x 8 blk x 64 u32
constexpr int SMEM_U32 = AS_TOT + 4 * BS_STAGE;   // 9216 u32 = 36 KB
}

// Persistent scratch (static __device__ allocation — sanctioned pattern).
__device__ __align__(16) unsigned g_Wp0[64 * 80 * 512];     // layer0 fp16-packed weights (B-frag layout)
__device__ __align__(16) unsigned g_Wp1[64 * 128 * 512];    // layer1
__device__ __align__(16) unsigned g_xs[XSZ];                // x as fp16 pairs, (t, n, kpair)
__device__ __align__(16) unsigned g_h0s[2][64 * 512];       // [parity] h layer0, fp16 pairs
__device__ __align__(16) unsigned g_h1s[2][64 * 512];       // h layer1
__device__ unsigned g_bar;                                  // grid barrier (monotonic)

// Pack fp32 pair into one u32 of fp16x2 (round-to-nearest).
DEVFN unsigned pack2h(float x0, float x1) {
    __half2 p = __floats2half2_rn(x0, x1);
    return *reinterpret_cast<unsigned*>(&p);
}

DEVFN void mma16816f(float* c, const unsigned* a, unsigned b0, unsigned b1) {
    asm volatile(
        "mma.sync.aligned.m16n8k16.row.col.f32.f16.f16.f32 "
        "{%0,%1,%2,%3}, {%4,%5,%6,%7}, {%8,%9}, {%0,%1,%2,%3};\n"
        : "+f"(c[0]), "+f"(c[1]), "+f"(c[2]), "+f"(c[3])
        : "r"(a[0]), "r"(a[1]), "r"(a[2]), "r"(a[3]), "r"(b0), "r"(b1));
}

DEVFN void cp16(void* sdst, const void* gsrc) {
    unsigned s = (unsigned)__cvta_generic_to_shared(sdst);
    asm volatile("cp.async.cg.shared.global [%0], [%1], 16;\n" :: "r"(s), "l"(gsrc));
}
DEVFN void cp_commit() { asm volatile("cp.async.commit_group;\n"); }
template <int N> DEVFN void cp_wait() { asm volatile("cp.async.wait_group %0;\n" :: "n"(N)); }

DEVFN float sigf(float x) { return 1.f / (1.f + __expf(-x)); }
DEVFN float tanhf_(float x) {
    float a = fabsf(x);
    float e = __expf(-2.f * a);
    return copysignf((1.f - e) / (1.f + e), x);
}

// ---------------------------------------------------------------------------
// Reset barrier + pack initial h state into the correct parity slots.
// layer0 reads parity 1 at epoch 0; layer1 reads parity 0 at epoch 1.
// ---------------------------------------------------------------------------
__global__ void init_kernel(const float* __restrict__ h0) {
    unsigned i = blockIdx.x * blockDim.x + threadIdx.x;
    if (i == 0) g_bar = 0u;
    const float2* h2 = (const float2*)h0;
    for (; i < 2u * 64u * 512u; i += gridDim.x * blockDim.x) {
        float2 v = h2[i];
        const unsigned p = pack2h(v.x, v.y);
        if (i < 64u * 512u) g_h0s[1][i] = p;
        else                g_h1s[0][i - 64u * 512u] = p;
    }
}

// Pack x into fp16 pairs, layout (t, n, kpair).
__global__ void xsplit_kernel(const float* __restrict__ x) {
    const float2* x2 = (const float2*)x;
    for (unsigned i = blockIdx.x * blockDim.x + threadIdx.x; i < XSZ;
         i += gridDim.x * blockDim.x) {
        float2 v = x2[i];
        g_xs[i] = pack2h(v.x, v.y);
    }
}

// ---------------------------------------------------------------------------
// Pack weights into mma-B-fragment-exact, gate-interleaved fp16 layout.
// u32 at ((c*S16+s)*8+blk)*64 + lane*2 + bsel packs fp16x2 of
// W[row][k0], W[row][k0+1] with k0 = s*16 + (lane&3)*2 + bsel*8,
// col = blk*8 + (lane>>2), gate = col>>4, cell = c*16 + (col&15),
// row = gate*H + cell;  k < Din -> w_ih else w_hh (K = [input ; hidden]).
// ---------------------------------------------------------------------------
__global__ void permute_kernel(
    const float* __restrict__ wih0, const float* __restrict__ whh0,
    const float* __restrict__ wih1, const float* __restrict__ whh1)
{
    const int tot0 = 64 * 80 * 512;
    const int tot1 = 64 * 128 * 512;
    for (int idx = blockIdx.x * blockDim.x + threadIdx.x; idx < tot0 + tot1;
         idx += gridDim.x * blockDim.x) {
        const int layer = idx >= tot0 ? 1 : 0;
        const int li = layer ? idx - tot0 : idx;
        const int S16 = layer ? 128 : 80;
        const int Din = layer ? HD : IND;
        const float* wih = layer ? wih1 : wih0;
        const float* whh = layer ? whh1 : whh0;
        const int per_c = S16 * 512;
        const int c = li / per_c;
        const int rem = li - c * per_c;
        const int s = rem >> 9;
        const int r2 = rem & 511;
        const int blk = r2 >> 6;
        const int r4 = r2 & 63;
        const int lane = r4 >> 1, bsel = r4 & 1;
        const int k0 = s * 16 + (lane & 3) * 2 + bsel * 8;
        const int col = blk * 8 + (lane >> 2);
        const int row = (col >> 4) * HD + c * 16 + (col & 15);
        float v0, v1;
        if (k0 < Din) { v0 = wih[row * Din + k0]; v1 = wih[row * Din + k0 + 1]; }
        else          { v0 = whh[row * HD + k0 - Din]; v1 = whh[row * HD + k0 + 1 - Din]; }
        const unsigned val = pack2h(v0, v1);
        if (layer) g_Wp1[li] = val;
        else       g_Wp0[li] = val;
    }
}

// ---------------------------------------------------------------------------
// Persistent LSTM. 128 CTAs x 128 threads. CTA = (layer = bid>>6, cblk = bid&63).
// Single-pass fp16 mma (16 HMMA/warp/chunk — 3x fewer than the bf16 split),
// fp32 accumulators + fp32 cell state: output error ~ fp16 eps only.
// 4-stage cp.async pipeline, one __syncthreads per 32-K chunk (R8 skeleton).
// ---------------------------------------------------------------------------
__global__ void __launch_bounds__(128, 1) lstm_kernel(
    const float* __restrict__ c0,
    const float* __restrict__ bih0, const float* __restrict__ bhh0,
    const float* __restrict__ bih1, const float* __restrict__ bhh1,
    float* __restrict__ out)
{
    extern __shared__ unsigned smem[];

    const int layer = blockIdx.x >> 6;
    const int cblk = blockIdx.x & 63;
    const int tid = threadIdx.x;
    const int w = tid >> 5, lane = tid & 31;
    const int g = lane >> 2, t = lane & 3;
    const int S16 = layer ? 128 : 80;
    const int nch = layer ? 64 : 40;     // 32-wide K chunks
    const unsigned* __restrict__ Wp = layer ? g_Wp1 : g_Wp0;
    const float* bih = layer ? bih1 : bih0;
    const float* bhh = layer ? bhh1 : bhh0;

    float2 bias[8];
#pragma unroll
    for (int blk = 0; blk < 8; blk++) {
        const int r = (blk >> 1) * HD + cblk * 16 + (blk & 1) * 8 + t * 2;
        bias[blk].x = bih[r] + bhh[r];
        bias[blk].y = bih[r + 1] + bhh[r + 1];
    }
    float cst[8];
#pragma unroll
    for (int rho = 0; rho < 2; rho++)
#pragma unroll
        for (int p = 0; p < 2; p++)
#pragma unroll
            for (int q = 0; q < 2; q++) {
                const int n = 16 * w + g + 8 * rho;
                const int cell = cblk * 16 + p * 8 + t * 2 + q;
                cst[rho * 4 + p * 2 + q] = c0[(unsigned)layer * NH + (unsigned)n * HD + cell];
            }

    for (int e = 0; e <= 512; e++) {
        const int tstep = layer ? e - 1 : e;
        const bool active = layer ? (e >= 1) : (e < 512);
        const int rs = 1 - (e & 1), ws = e & 1;
        if (active) {
            float acc[8][4];
#pragma unroll
            for (int blk = 0; blk < 8; blk++) {
                acc[blk][0] = acc[blk][2] = bias[blk].x;
                acc[blk][1] = acc[blk][3] = bias[blk].y;
            }

            auto load_chunk = [&](int ch) {
                const int kp0 = ch * 16;                 // fp16-pair offset
                unsigned* sb = smem + (ch & 3) * AS_STAGE;
                unsigned* bb = smem + AS_TOT + (ch & 3) * BS_STAGE;
                const unsigned* bsrc = Wp + ((unsigned)cblk * S16 + ch * 2) * 512u;
#pragma unroll
                for (int i = 0; i < 2; i++) {
                    const int id = tid + i * 128;        // 0..255
                    const int row = id >> 2, seg = id & 3;
                    const unsigned* asrc;
                    if (layer == 0) {
                        if (kp0 < 128)
                            asrc = g_xs + ((unsigned)tstep * 64 + row) * 128 + kp0;
                        else
                            asrc = g_h0s[rs] + row * 512 + (kp0 - 128);
                    } else {
                        if (kp0 < 512)
                            asrc = g_h0s[rs] + row * 512 + kp0;
                        else
                            asrc = g_h1s[rs] + row * 512 + (kp0 - 512);
                    }
                    cp16(sb + row * 20 + seg * 4, asrc + seg * 4);
                    cp16(bb + id * 4, bsrc + id * 4);
                }
                cp_commit();
            };

            load_chunk(0);
            load_chunk(1);
            load_chunk(2);
            for (int ch = 0; ch < nch; ch++) {
                cp_wait<2>();           // chunk ch's group complete (this thread)
                __syncthreads();        // visible to all; stage (ch-1)&3 free
                if (ch + 3 < nch) load_chunk(ch + 3);
                else cp_commit();       // keep group count constant
                const int buf = ch & 3;
                const unsigned* as_ = smem + buf * AS_STAGE;
                const unsigned* bs_ = smem + AS_TOT + buf * BS_STAGE;
                const int arow = (16 * w + g) * 20;
#pragma unroll
                for (int sl = 0; sl < 2; sl++) {
                    const int ab = arow + sl * 8 + t;
                    unsigned a[4];
                    a[0] = as_[ab];        a[1] = as_[ab + 160];
                    a[2] = as_[ab + 4];    a[3] = as_[ab + 164];
#pragma unroll
                    for (int blk = 0; blk < 8; blk++) {
                        const unsigned* bb2 = bs_ + (sl * 8 + blk) * 64 + lane * 2;
                        const uint2 bv = *(const uint2*)bb2;
                        mma16816f(acc[blk], a, bv.x, bv.y);
                    }
                }
            }
            __syncthreads();   // last stage consumed before epilogue/next reuse

            // Fused LSTM pointwise epilogue; h stored as fp16 pairs.
            unsigned* hs = layer ? g_h1s[ws] : g_h0s[ws];
#pragma unroll
            for (int rho = 0; rho < 2; rho++) {
                const int n = 16 * w + g + 8 * rho;
#pragma unroll
                for (int p = 0; p < 2; p++) {
                    const int cell = cblk * 16 + p * 8 + t * 2;
                    float2 h2, c2;
#pragma unroll
                    for (int q = 0; q < 2; q++) {
                        const int idx = rho * 2 + q;
                        const float ii = sigf(acc[0 + p][idx]);
                        const float ff = sigf(acc[2 + p][idx]);
                        const float gg = tanhf_(acc[4 + p][idx]);
                        const float oo = sigf(acc[6 + p][idx]);
                        const int cs = rho * 4 + p * 2 + q;
                        const float cc = ff * cst[cs] + ii * gg;
                        cst[cs] = cc;
                        const float hh = oo * tanhf_(cc);
                        if (q) { h2.y = hh; c2.y = cc; } else { h2.x = hh; c2.x = cc; }
                    }
                    hs[(unsigned)n * 512 + (cell >> 1)] = pack2h(h2.x, h2.y);
                    *(float2*)&out[ALLC_OFF + ((unsigned)(tstep * 2 + layer) * NB + n) * HD + cell] = c2;
                    if (layer)
                        *(float2*)&out[((unsigned)tstep * NB + n) * HD + cell] = h2;
                    if (tstep == 511) {
                        *(float2*)&out[HN_OFF + ((unsigned)layer * NB + n) * HD + cell] = h2;
                        *(float2*)&out[CN_OFF + ((unsigned)layer * NB + n) * HD + cell] = c2;
                    }
                }
            }
        }
        if (e < 512) {   // grid barrier (monotonic; init resets g_bar)
            __threadfence();
            __syncthreads();
            if (tid == 0) {
                atomicAdd(&g_bar, 1u);
                const unsigned target = (unsigned)(e + 1) * 128u;
                unsigned v;
                do {
                    asm volatile("ld.acquire.gpu.u32 %0, [%1];" : "=r"(v) : "l"(&g_bar));
                    if (v >= target) break;
                    __nanosleep(32);
                } while (true);
            }
            __syncthreads();
        }
    }
}

extern "C" void kernel_launch(void* const* d_in, const int* in_sizes, int n_in,
                              void* d_out, int out_size) {
    (void)in_sizes; (void)n_in; (void)out_size;
    const float* x    = (const float*)d_in[0];
    const float* h0   = (const float*)d_in[1];
    const float* c0   = (const float*)d_in[2];
    const float* wih0 = (const float*)d_in[3];
    const float* whh0 = (const float*)d_in[4];
    const float* bih0 = (const float*)d_in[5];
    const float* bhh0 = (const float*)d_in[6];
    const float* wih1 = (const float*)d_in[7];
    const float* whh1 = (const float*)d_in[8];
    const float* bih1 = (const float*)d_in[9];
    const float* bhh1 = (const float*)d_in[10];
    float* out = (float*)d_out;

    static bool attr_set = false;
    if (!attr_set) {
        cudaFuncSetAttribute(lstm_kernel, cudaFuncAttributeMaxDynamicSharedMemorySize,
                             SMEM_U32 * 4);
        attr_set = true;
    }

    init_kernel<<<64, 256>>>(h0);
    xsplit_kernel<<<2048, 256>>>(x);
    permute_kernel<<<4096, 256>>>(wih0, whh0, wih1, whh1);
    lstm_kernel<<<128, 128, SMEM_U32 * 4>>>(c0, bih0, bhh0, bih1, bhh1, out);
}

// round 17
// speedup vs baseline: 2.1816x; 1.2213x over previous
#include <cuda_runtime.h>
#include <cuda_fp16.h>

#define DEVFN static __device__ __forceinline__

namespace {
constexpr int L_ = 512, NB = 64, IND = 256, HD = 1024;
constexpr unsigned NH = (unsigned)NB * HD;                        // 65536
constexpr unsigned ALLC_OFF = (unsigned)L_ * NH;                  // 33554432
constexpr unsigned HN_OFF = ALLC_OFF + (unsigned)L_ * 2u * NH;    // 100663296
constexpr unsigned CN_OFF = HN_OFF + 2u * NH;
constexpr unsigned XSZ = (unsigned)L_ * NB * (IND / 2);           // 4194304 u32 (fp16 pairs)
// dynamic smem layout (u32 units), 64-wide K chunks
constexpr int AS_STAGE = 64 * 36;          // 64 rows x (32 data pairs + 4 pad)
constexpr int AS_TOT   = 4 * AS_STAGE;     // 9216
constexpr int BS_STAGE = 2048;             // 4 k16-steps x 8 blk x 64 u32
constexpr int SMEM_U32 = AS_TOT + 4 * BS_STAGE;   // 17408 u32 = 68 KB
}

// Persistent scratch (static __device__ allocation — sanctioned pattern).
__device__ __align__(16) unsigned g_Wp0[64 * 20 * 2048];    // layer0 fp16 weights (B-frag layout)
__device__ __align__(16) unsigned g_Wp1[64 * 32 * 2048];    // layer1
__device__ __align__(16) unsigned g_xs[XSZ];                // x as fp16 pairs, (t, n, kpair)
__device__ __align__(16) unsigned g_h0s[2][64 * 512];       // [parity] h layer0, fp16 pairs
__device__ __align__(16) unsigned g_h1s[2][64 * 512];       // h layer1
__device__ __align__(16) float g_part[64][2][128][32];      // K-split partials [unit][par][tid][32]
__device__ unsigned g_pflag[64];                            // partial-ready epoch flags
__device__ unsigned g_bar;                                  // grid barrier (monotonic)

// Pack fp32 pair into one u32 of fp16x2 (round-to-nearest).
DEVFN unsigned pack2h(float x0, float x1) {
    __half2 p = __floats2half2_rn(x0, x1);
    return *reinterpret_cast<unsigned*>(&p);
}

DEVFN void mma16816f(float* c, const unsigned* a, unsigned b0, unsigned b1) {
    asm volatile(
        "mma.sync.aligned.m16n8k16.row.col.f32.f16.f16.f32 "
        "{%0,%1,%2,%3}, {%4,%5,%6,%7}, {%8,%9}, {%0,%1,%2,%3};\n"
        : "+f"(c[0]), "+f"(c[1]), "+f"(c[2]), "+f"(c[3])
        : "r"(a[0]), "r"(a[1]), "r"(a[2]), "r"(a[3]), "r"(b0), "r"(b1));
}

DEVFN void cp16(void* sdst, const void* gsrc) {
    unsigned s = (unsigned)__cvta_generic_to_shared(sdst);
    asm volatile("cp.async.cg.shared.global [%0], [%1], 16;\n" :: "r"(s), "l"(gsrc));
}
DEVFN void cp_commit() { asm volatile("cp.async.commit_group;\n"); }
template <int N> DEVFN void cp_wait() { asm volatile("cp.async.wait_group %0;\n" :: "n"(N)); }

DEVFN float sigf(float x) { return 1.f / (1.f + __expf(-x)); }
DEVFN float tanhf_(float x) {
    float a = fabsf(x);
    float e = __expf(-2.f * a);
    return copysignf((1.f - e) / (1.f + e), x);
}

// ---------------------------------------------------------------------------
// Reset barrier + flags, pack initial h state into the correct parity slots.
// layer0 reads parity 1 at epoch 0; layer1 reads parity 0 at epoch 1.
// ---------------------------------------------------------------------------
__global__ void init_kernel(const float* __restrict__ h0) {
    unsigned i = blockIdx.x * blockDim.x + threadIdx.x;
    if (i == 0) g_bar = 0u;
    if (blockIdx.x == 0 && threadIdx.x < 64) g_pflag[threadIdx.x] = 0u;
    const float2* h2 = (const float2*)h0;
    for (; i < 2u * 64u * 512u; i += gridDim.x * blockDim.x) {
        float2 v = h2[i];
        const unsigned p = pack2h(v.x, v.y);
        if (i < 64u * 512u) g_h0s[1][i] = p;
        else                g_h1s[0][i - 64u * 512u] = p;
    }
}

// Pack x into fp16 pairs, layout (t, n, kpair).
__global__ void xsplit_kernel(const float* __restrict__ x) {
    const float2* x2 = (const float2*)x;
    for (unsigned i = blockIdx.x * blockDim.x + threadIdx.x; i < XSZ;
         i += gridDim.x * blockDim.x) {
        float2 v = x2[i];
        g_xs[i] = pack2h(v.x, v.y);
    }
}

// ---------------------------------------------------------------------------
// Pack weights into mma-B-fragment-exact, gate-interleaved fp16 layout.
// u32 at ((c*S16+s)*8+blk)*64 + lane*2 + bsel packs fp16x2 of
// W[row][k0], W[row][k0+1] with k0 = s*16 + (lane&3)*2 + bsel*8,
// col = blk*8 + (lane>>2), gate = col>>4, cell = c*16 + (col&15),
// row = gate*H + cell;  k < Din -> w_ih else w_hh (K = [input ; hidden]).
// ---------------------------------------------------------------------------
__global__ void permute_kernel(
    const float* __restrict__ wih0, const float* __restrict__ whh0,
    const float* __restrict__ wih1, const float* __restrict__ whh1)
{
    const int tot0 = 64 * 80 * 512;
    const int tot1 = 64 * 128 * 512;
    for (int idx = blockIdx.x * blockDim.x + threadIdx.x; idx < tot0 + tot1;
         idx += gridDim.x * blockDim.x) {
        const int layer = idx >= tot0 ? 1 : 0;
        const int li = layer ? idx - tot0 : idx;
        const int S16 = layer ? 128 : 80;
        const int Din = layer ? HD : IND;
        const float* wih = layer ? wih1 : wih0;
        const float* whh = layer ? whh1 : whh0;
        const int per_c = S16 * 512;
        const int c = li / per_c;
        const int rem = li - c * per_c;
        const int s = rem >> 9;
        const int r2 = rem & 511;
        const int blk = r2 >> 6;
        const int r4 = r2 & 63;
        const int lane = r4 >> 1, bsel = r4 & 1;
        const int k0 = s * 16 + (lane & 3) * 2 + bsel * 8;
        const int col = blk * 8 + (lane >> 2);
        const int row = (col >> 4) * HD + c * 16 + (col & 15);
        float v0, v1;
        if (k0 < Din) { v0 = wih[row * Din + k0]; v1 = wih[row * Din + k0 + 1]; }
        else          { v0 = whh[row * HD + k0 - Din]; v1 = whh[row * HD + k0 + 1 - Din]; }
        const unsigned val = pack2h(v0, v1);
        if (layer) g_Wp1[li] = val;
        else       g_Wp0[li] = val;
    }
}

// ---------------------------------------------------------------------------
// Persistent LSTM, fp16, balanced. 128 CTAs x 128 threads.
// 64-wide K chunks: layer0 K=1280 -> 20 chunks; layer1 K=2048 -> 32 chunks.
// layer0 CTA j: per epoch, first compute chunks 26..31 of layer1 unit j
// (zero-init fp32 partials -> g_part + release flag), then its own 20 chunks.
// layer1 CTA j: chunks 0..25, acquire flag, merge partials, fused epilogue.
// Every CTA: 26 chunks/epoch.
// ---------------------------------------------------------------------------
__global__ void __launch_bounds__(128, 1) lstm_kernel(
    const float* __restrict__ c0,
    const float* __restrict__ bih0, const float* __restrict__ bhh0,
    const float* __restrict__ bih1, const float* __restrict__ bhh1,
    float* __restrict__ out)
{
    extern __shared__ unsigned smem[];

    const int layer = blockIdx.x >> 6;
    const int cblk = blockIdx.x & 63;
    const int tid = threadIdx.x;
    const int w = tid >> 5, lane = tid & 31;
    const int g = lane >> 2, t = lane & 3;
    const float* bih = layer ? bih1 : bih0;
    const float* bhh = layer ? bhh1 : bhh0;
    const unsigned* Wown = layer ? (g_Wp1 + (unsigned)cblk * 65536u)
                                 : (g_Wp0 + (unsigned)cblk * 40960u);
    const unsigned* Whelp = g_Wp1 + (unsigned)cblk * 65536u;   // l1 unit j (used by l0)

    float2 bias[8];
#pragma unroll
    for (int blk = 0; blk < 8; blk++) {
        const int r = (blk >> 1) * HD + cblk * 16 + (blk & 1) * 8 + t * 2;
        bias[blk].x = bih[r] + bhh[r];
        bias[blk].y = bih[r + 1] + bhh[r + 1];
    }
    float cst[8];
#pragma unroll
    for (int rho = 0; rho < 2; rho++)
#pragma unroll
        for (int p = 0; p < 2; p++)
#pragma unroll
            for (int q = 0; q < 2; q++) {
                const int n = 16 * w + g + 8 * rho;
                const int cell = cblk * 16 + p * 8 + t * 2 + q;
                cst[rho * 4 + p * 2 + q] = c0[(unsigned)layer * NH + (unsigned)n * HD + cell];
            }

    for (int e = 0; e <= 512; e++) {
        const int rs = 1 - (e & 1), ws = e & 1;

        // A-source for a 64-pair chunk of layer aL (x step index = e for l0).
        auto load_chunk = [&](int ch, int aL, const unsigned* Wb) {
            const int kp0 = ch * 32;                    // fp16-pair offset
            unsigned* sb = smem + (ch & 3) * AS_STAGE;
            unsigned* bb = smem + AS_TOT + (ch & 3) * BS_STAGE;
            const unsigned* bsrc = Wb + (unsigned)ch * 2048u;
#pragma unroll
            for (int i = 0; i < 4; i++) {
                const int id = tid + i * 128;           // 0..511
                const int row = id >> 3, seg = id & 7;  // 64 rows x 8 segs
                const unsigned* asrc;
                if (aL == 0) {
                    if (kp0 < 128)
                        asrc = g_xs + ((unsigned)e * 64 + row) * 128 + kp0;
                    else
                        asrc = g_h0s[rs] + row * 512 + (kp0 - 128);
                } else {
                    if (kp0 < 512)
                        asrc = g_h0s[rs] + row * 512 + kp0;
                    else
                        asrc = g_h1s[rs] + row * 512 + (kp0 - 512);
                }
                cp16(sb + row * 36 + seg * 4, asrc + seg * 4);
                cp16(bb + id * 4, bsrc + id * 4);
            }
            cp_commit();
        };
        auto gemm_range = [&](int cA, int cB, int aL, const unsigned* Wb,
                              float (*acc)[4]) {
            load_chunk(cA, aL, Wb);
            load_chunk(cA + 1, aL, Wb);
            load_chunk(cA + 2, aL, Wb);
            for (int ch = cA; ch < cB; ch++) {
                cp_wait<2>();           // chunk ch's group complete (this thread)
                __syncthreads();        // visible to all; stage (ch-1)&3 free
                if (ch + 3 < cB) load_chunk(ch + 3, aL, Wb);
                else cp_commit();       // keep group count constant
                const int buf = ch & 3;
                const unsigned* as_ = smem + buf * AS_STAGE;
                const unsigned* bs_ = smem + AS_TOT + buf * BS_STAGE;
                const int arow = (16 * w + g) * 36;
#pragma unroll
                for (int sl = 0; sl < 4; sl++) {
                    const int ab = arow + sl * 8 + t;
                    unsigned a[4];
                    a[0] = as_[ab];        a[1] = as_[ab + 288];
                    a[2] = as_[ab + 4];    a[3] = as_[ab + 292];
#pragma unroll
                    for (int blk = 0; blk < 8; blk++) {
                        const unsigned* bb2 = bs_ + (sl * 8 + blk) * 64 + lane * 2;
                        const uint2 bv = *(const uint2*)bb2;
                        mma16816f(acc[blk], a, bv.x, bv.y);
                    }
                }
            }
            cp_wait<0>();
            __syncthreads();
        };

        if (layer == 0) {
            // ---- helper: chunks 26..31 of layer1 unit cblk (step e-1) ----
            if (e >= 1) {
                float hacc[8][4];
#pragma unroll
                for (int blk = 0; blk < 8; blk++)
#pragma unroll
                    for (int i = 0; i < 4; i++) hacc[blk][i] = 0.f;
                gemm_range(26, 32, 1, Whelp, hacc);
                float4* pb = (float4*)g_part[cblk][e & 1][tid];
#pragma unroll
                for (int blk = 0; blk < 8; blk++)
                    pb[blk] = make_float4(hacc[blk][0], hacc[blk][1], hacc[blk][2], hacc[blk][3]);
                __threadfence();
                __syncthreads();
                if (tid == 0)
                    asm volatile("st.release.gpu.u32 [%0], %1;"
                                 :: "l"(&g_pflag[cblk]), "r"((unsigned)e) : "memory");
            }
            // ---- own layer0 work: 20 chunks, step e ----
            if (e < 512) {
                float acc[8][4];
#pragma unroll
                for (int blk = 0; blk < 8; blk++) {
                    acc[blk][0] = acc[blk][2] = bias[blk].x;
                    acc[blk][1] = acc[blk][3] = bias[blk].y;
                }
                gemm_range(0, 20, 0, Wown, acc);
                unsigned* hs = g_h0s[ws];
#pragma unroll
                for (int rho = 0; rho < 2; rho++) {
                    const int n = 16 * w + g + 8 * rho;
#pragma unroll
                    for (int p = 0; p < 2; p++) {
                        const int cell = cblk * 16 + p * 8 + t * 2;
                        float2 h2, c2;
#pragma unroll
                        for (int q = 0; q < 2; q++) {
                            const int idx = rho * 2 + q;
                            const float ii = sigf(acc[0 + p][idx]);
                            const float ff = sigf(acc[2 + p][idx]);
                            const float gg = tanhf_(acc[4 + p][idx]);
                            const float oo = sigf(acc[6 + p][idx]);
                            const int cs = rho * 4 + p * 2 + q;
                            const float cc = ff * cst[cs] + ii * gg;
                            cst[cs] = cc;
                            const float hh = oo * tanhf_(cc);
                            if (q) { h2.y = hh; c2.y = cc; } else { h2.x = hh; c2.x = cc; }
                        }
                        hs[(unsigned)n * 512 + (cell >> 1)] = pack2h(h2.x, h2.y);
                        *(float2*)&out[ALLC_OFF + ((unsigned)(e * 2 + 0) * NB + n) * HD + cell] = c2;
                        if (e == 511) {
                            *(float2*)&out[HN_OFF + ((unsigned)n) * HD + cell] = h2;
                            *(float2*)&out[CN_OFF + ((unsigned)n) * HD + cell] = c2;
                        }
                    }
                }
            }
        } else if (e >= 1) {
            // ---- layer1: chunks 0..25, then merge partials (step e-1) ----
            const int tstep = e - 1;
            float acc[8][4];
#pragma unroll
            for (int blk = 0; blk < 8; blk++) {
                acc[blk][0] = acc[blk][2] = bias[blk].x;
                acc[blk][1] = acc[blk][3] = bias[blk].y;
            }
            gemm_range(0, 26, 1, Wown, acc);
            if (tid == 0) {
                unsigned v;
                do {
                    asm volatile("ld.acquire.gpu.u32 %0, [%1];" : "=r"(v) : "l"(&g_pflag[cblk]));
                    if (v >= (unsigned)e) break;
                    __nanosleep(32);
                } while (true);
            }
            __syncthreads();
            const float4* pb = (const float4*)g_part[cblk][e & 1][tid];
#pragma unroll
            for (int blk = 0; blk < 8; blk++) {
                const float4 pv = pb[blk];
                acc[blk][0] += pv.x; acc[blk][1] += pv.y;
                acc[blk][2] += pv.z; acc[blk][3] += pv.w;
            }
            unsigned* hs = g_h1s[ws];
#pragma unroll
            for (int rho = 0; rho < 2; rho++) {
                const int n = 16 * w + g + 8 * rho;
#pragma unroll
                for (int p = 0; p < 2; p++) {
                    const int cell = cblk * 16 + p * 8 + t * 2;
                    float2 h2, c2;
#pragma unroll
                    for (int q = 0; q < 2; q++) {
                        const int idx = rho * 2 + q;
                        const float ii = sigf(acc[0 + p][idx]);
                        const float ff = sigf(acc[2 + p][idx]);
                        const float gg = tanhf_(acc[4 + p][idx]);
                        const float oo = sigf(acc[6 + p][idx]);
                        const int cs = rho * 4 + p * 2 + q;
                        const float cc = ff * cst[cs] + ii * gg;
                        cst[cs] = cc;
                        const float hh = oo * tanhf_(cc);
                        if (q) { h2.y = hh; c2.y = cc; } else { h2.x = hh; c2.x = cc; }
                    }
                    hs[(unsigned)n * 512 + (cell >> 1)] = pack2h(h2.x, h2.y);
                    *(float2*)&out[ALLC_OFF + ((unsigned)(tstep * 2 + 1) * NB + n) * HD + cell] = c2;
                    *(float2*)&out[((unsigned)tstep * NB + n) * HD + cell] = h2;
                    if (tstep == 511) {
                        *(float2*)&out[HN_OFF + ((unsigned)NB + n) * HD + cell] = h2;
                        *(float2*)&out[CN_OFF + ((unsigned)NB + n) * HD + cell] = c2;
                    }
                }
            }
        }

        if (e < 512) {   // grid barrier (monotonic; init resets g_bar)
            __threadfence();
            __syncthreads();
            if (tid == 0) {
                atomicAdd(&g_bar, 1u);
                const unsigned target = (unsigned)(e + 1) * 128u;
                unsigned v;
                do {
                    asm volatile("ld.acquire.gpu.u32 %0, [%1];" : "=r"(v) : "l"(&g_bar));
                    if (v >= target) break;
                    __nanosleep(32);
                } while (true);
            }
            __syncthreads();
        }
    }
}

extern "C" void kernel_launch(void* const* d_in, const int* in_sizes, int n_in,
                              void* d_out, int out_size) {
    (void)in_sizes; (void)n_in; (void)out_size;
    const float* x    = (const float*)d_in[0];
    const float* h0   = (const float*)d_in[1];
    const float* c0   = (const float*)d_in[2];
    const float* wih0 = (const float*)d_in[3];
    const float* whh0 = (const float*)d_in[4];
    const float* bih0 = (const float*)d_in[5];
    const float* bhh0 = (const float*)d_in[6];
    const float* wih1 = (const float*)d_in[7];
    const float* whh1 = (const float*)d_in[8];
    const float* bih1 = (const float*)d_in[9];
    const float* bhh1 = (const float*)d_in[10];
    float* out = (float*)d_out;

    static bool attr_set = false;
    if (!attr_set) {
        cudaFuncSetAttribute(lstm_kernel, cudaFuncAttributeMaxDynamicSharedMemorySize,
                             SMEM_U32 * 4);
        attr_set = true;
    }

    init_kernel<<<64, 256>>>(h0);
    xsplit_kernel<<<2048, 256>>>(x);
    permute_kernel<<<4096, 256>>>(wih0, whh0, wih1, whh1);
    lstm_kernel<<<128, 128, SMEM_U32 * 4>>>(c0, bih0, bhh0, bih1, bhh1, out);
}